// round 4
// baseline (speedup 1.0000x reference)
#include <cuda_runtime.h>
#include <cuda_fp16.h>
#include <cstdint>

#define N_NODES 100000
#define KK 5
#define CC 16
#define EE 3200000
#define PPK (EE / 4)                  // 800,000 int4-packs per k
#define PTOT (KK * PPK)               // 4,000,000 packs
#define NT 1024
#define PSTAGE 256                    // packs per pipeline stage (1024 edges)

// smem layout (bytes)
#define SLICE_BYTES (N_NODES * 2)                 // 200,000 fp16 Z slice
#define OFF_ROWS  SLICE_BYTES                     // 2 stages x 256 int4 = 8192
#define OFF_COLS  (OFF_ROWS + 2 * PSTAGE * 16)    // 208,192
#define OFF_VALS  (OFF_COLS + 2 * PSTAGE * 16)    // 216,384
#define OFF_MBAR  (OFF_VALS + 2 * PSTAGE * 16)    // 224,576
#define SMEM_TOTAL (OFF_MBAR + 16)                // 224,592

__device__ __half g_Zt[KK * N_NODES];

__device__ __forceinline__ uint32_t s2u(const void* p) {
    uint32_t a;
    asm("{ .reg .u64 t; cvta.to.shared.u64 t, %1; cvt.u32.u64 %0, t; }"
        : "=r"(a) : "l"(p));
    return a;
}

__device__ __forceinline__ void mbar_init(uint32_t mbar, uint32_t count) {
    asm volatile("mbarrier.init.shared::cta.b64 [%0], %1;" :: "r"(mbar), "r"(count) : "memory");
}
__device__ __forceinline__ void mbar_expect_tx(uint32_t mbar, uint32_t tx) {
    asm volatile("mbarrier.arrive.expect_tx.shared::cta.b64 _, [%0], %1;"
                 :: "r"(mbar), "r"(tx) : "memory");
}
__device__ __forceinline__ void bulk_g2s(uint32_t dst, const void* src, uint32_t bytes, uint32_t mbar) {
    asm volatile("cp.async.bulk.shared::cta.global.mbarrier::complete_tx::bytes [%0], [%1], %2, [%3];"
                 :: "r"(dst), "l"(src), "r"(bytes), "r"(mbar) : "memory");
}
__device__ __forceinline__ void mbar_wait(uint32_t mbar, uint32_t phase) {
    uint32_t done;
    asm volatile(
        "{\n\t.reg .pred p;\n\t"
        "mbarrier.try_wait.parity.acquire.cta.shared::cta.b64 p, [%1], %2, 0x989680;\n\t"
        "selp.b32 %0, 1, 0, p;\n\t}"
        : "=r"(done) : "r"(mbar), "r"(phase) : "memory");
    while (!done) {
        asm volatile(
            "{\n\t.reg .pred p;\n\t"
            "mbarrier.try_wait.parity.acquire.cta.shared::cta.b64 p, [%1], %2, 0x989680;\n\t"
            "selp.b32 %0, 1, 0, p;\n\t}"
            : "=r"(done) : "r"(mbar), "r"(phase) : "memory");
    }
}

// Kernel 1: Z = X @ h (k-major, fp16), and zero y (d_out is poisoned).
__global__ __launch_bounds__(256) void compute_z_kernel(
    const float* __restrict__ X,
    const float* __restrict__ h,
    float* __restrict__ y)
{
    __shared__ float hs[CC * KK];
    if (threadIdx.x < CC * KK) hs[threadIdx.x] = h[threadIdx.x];
    __syncthreads();

    int n = blockIdx.x * blockDim.x + threadIdx.x;
    if (n >= N_NODES) return;

    float x[CC];
    const float4* xp = reinterpret_cast<const float4*>(X + (size_t)n * CC);
#pragma unroll
    for (int i = 0; i < CC / 4; i++) {
        float4 v = xp[i];
        x[4*i+0] = v.x; x[4*i+1] = v.y; x[4*i+2] = v.z; x[4*i+3] = v.w;
    }
#pragma unroll
    for (int k = 0; k < KK; k++) {
        float acc = 0.f;
#pragma unroll
        for (int c = 0; c < CC; c++) acc += x[c] * hs[c * KK + k];
        g_Zt[k * N_NODES + n] = __float2half_rn(acc);
    }
    y[n] = 0.f;
}

// Kernel 2: TMA-staged streams + smem Z gather; L1tex path reserved for REDG.
__global__ __launch_bounds__(NT, 1) void scatter_kernel(
    const int4*   __restrict__ rows,
    const int4*   __restrict__ cols,
    const float4* __restrict__ vals,
    float* __restrict__ y)
{
    extern __shared__ __align__(16) char smem[];
    __half* sZ = reinterpret_cast<__half*>(smem);
    const int4*   sRows = reinterpret_cast<const int4*>(smem + OFF_ROWS);
    const int4*   sCols = reinterpret_cast<const int4*>(smem + OFF_COLS);
    const float4* sVals = reinterpret_cast<const float4*>(smem + OFF_VALS);

    const uint32_t sbase = s2u(smem);
    const uint32_t mbar0 = sbase + OFF_MBAR;      // two full-barriers, 8B each
    const int tid = threadIdx.x;

    if (tid == 0) { mbar_init(mbar0, 1); mbar_init(mbar0 + 8, 1); }
    __syncthreads();

    int ph[2] = {0, 0};

    long long bid = blockIdx.x, nb = gridDim.x;
    int p   = (int)((bid * PTOT) / nb);
    int end = (int)(((bid + 1) * PTOT) / nb);

    while (p < end) {
        int k    = p / PPK;
        int kend = (k + 1) * PPK; if (kend > end) kend = end;

        // Stage Z slice k into smem.
        __syncthreads();
        {
            const int4* src = reinterpret_cast<const int4*>(g_Zt + (size_t)k * N_NODES);
            int4* dst = reinterpret_cast<int4*>(sZ);
            for (int i = tid; i < SLICE_BYTES / 16; i += NT) dst[i] = src[i];
        }
        __syncthreads();

        const int n   = kend - p;
        const int nst = (n + PSTAGE - 1) / PSTAGE;

        // Prologue: issue stage 0.
        if (tid == 0) {
            int sn = n < PSTAGE ? n : PSTAGE;
            uint32_t bytes = (uint32_t)sn * 16u;
            mbar_expect_tx(mbar0, 3u * bytes);
            bulk_g2s(sbase + OFF_ROWS, rows + p, bytes, mbar0);
            bulk_g2s(sbase + OFF_COLS, cols + p, bytes, mbar0);
            bulk_g2s(sbase + OFF_VALS, vals + p, bytes, mbar0);
        }

        for (int j = 0; j < nst; j++) {
            // Issue stage j+1 into the other buffer (safe: its previous stage
            // j-1 was fully consumed before last iteration's __syncthreads).
            if (tid == 0 && j + 1 < nst) {
                int b1 = (j + 1) & 1;
                int g  = p + (j + 1) * PSTAGE;
                int sn = n - (j + 1) * PSTAGE; if (sn > PSTAGE) sn = PSTAGE;
                uint32_t bytes = (uint32_t)sn * 16u;
                uint32_t mb = mbar0 + 8u * b1;
                uint32_t boff = (uint32_t)(b1 * PSTAGE * 16);
                mbar_expect_tx(mb, 3u * bytes);
                bulk_g2s(sbase + OFF_ROWS + boff, rows + g, bytes, mb);
                bulk_g2s(sbase + OFF_COLS + boff, cols + g, bytes, mb);
                bulk_g2s(sbase + OFF_VALS + boff, vals + g, bytes, mb);
            }

            const int b = j & 1;
            mbar_wait(mbar0 + 8u * b, ph[b]);
            ph[b] ^= 1;

            int sn = n - j * PSTAGE; if (sn > PSTAGE) sn = PSTAGE;
            if (tid < sn) {
                int idx = b * PSTAGE + tid;
                int4   r = sRows[idx];
                int4   c = sCols[idx];
                float4 v = sVals[idx];

                float z0 = __half2float(sZ[c.x]);
                float z1 = __half2float(sZ[c.y]);
                float z2 = __half2float(sZ[c.z]);
                float z3 = __half2float(sZ[c.w]);

                atomicAdd(&y[r.x], v.x * z0);
                atomicAdd(&y[r.y], v.y * z1);
                atomicAdd(&y[r.z], v.z * z2);
                atomicAdd(&y[r.w], v.w * z3);
            }
            __syncthreads();   // buffer b free for reuse
        }
        p = kend;
    }
}

extern "C" void kernel_launch(void* const* d_in, const int* in_sizes, int n_in,
                              void* d_out, int out_size) {
    const float* X    = (const float*)d_in[0];
    const int*   rows = (const int*)d_in[1];
    const int*   cols = (const int*)d_in[2];
    const float* vals = (const float*)d_in[3];
    const float* h    = (const float*)d_in[4];
    float* y = (float*)d_out;

    {
        int threads = 256;
        int blocks = (N_NODES + threads - 1) / threads;
        compute_z_kernel<<<blocks, threads>>>(X, h, y);
    }
    {
        static int sms = 0;
        if (sms == 0) {
            cudaDeviceGetAttribute(&sms, cudaDevAttrMultiProcessorCount, 0);
            if (sms <= 0) sms = 148;
            cudaFuncSetAttribute(scatter_kernel,
                                 cudaFuncAttributeMaxDynamicSharedMemorySize,
                                 SMEM_TOTAL);
        }
        scatter_kernel<<<sms, NT, SMEM_TOTAL>>>(
            (const int4*)rows, (const int4*)cols, (const float4*)vals, y);
    }
}